// round 12
// baseline (speedup 1.0000x reference)
#include <cuda_runtime.h>
#include <cstdint>
#include <cstddef>

#define N_ATOMS 10000
#define N_PAIRS 250000
#define NP 128
#define NO 128

#define PXNEW_OFF ((size_t)0)
#define IX_OFF    ((size_t)N_ATOMS * 3 * NP)
#define DOT_OFF   (IX_OFF + (size_t)N_PAIRS * 3 * NP)

#define BCAP 128   // per-atom bucket capacity; P(Poisson(25) >= 128) ~ 1e-45

// ---- device scratch (allocation-free; zero-initialized at load) ----
__device__ int g_cursor[N_ATOMS];           // invariant: zero at entry (k_main end-resets)
__device__ int g_bucket[N_ATOMS][BCAP];

// ---------------------------------------------------------------------------
// packed f32x2 helpers (sm_103a; ptxas never emits these from C++)
typedef unsigned long long ull;
union U4 { float4 f; ulonglong2 u; };
union U2 { float2 f; ull u; };

__device__ __forceinline__ ull a2(ull a, ull b) {
    ull c; asm("add.rn.f32x2 %0,%1,%2;" : "=l"(c) : "l"(a), "l"(b)); return c;
}
__device__ __forceinline__ ull m2(ull a, ull b) {
    ull c; asm("mul.rn.f32x2 %0,%1,%2;" : "=l"(c) : "l"(a), "l"(b)); return c;
}
__device__ __forceinline__ ull fma2(ull a, ull b, ull c) {
    ull d; asm("fma.rn.f32x2 %0,%1,%2,%3;" : "=l"(d) : "l"(a), "l"(b), "l"(c)); return d;
}

// v = (p + dd) * s ; acc += v   (element-wise identical to scalar FADD/FMUL/FADD)
__device__ __forceinline__ float4 row_op(float4 p, ull dd, const U4& s, U4& acc) {
    U4 P, V;
    P.f = p;
    V.u.x = m2(a2(P.u.x, dd), s.u.x);
    V.u.y = m2(a2(P.u.y, dd), s.u.y);
    acc.u.x = a2(acc.u.x, V.u.x);
    acc.u.y = a2(acc.u.y, V.u.y);
    return V.f;
}

// ---------------------------------------------------------------------------
// single-kernel CSR replacement: scatter pair ids into fixed-capacity buckets
__global__ void k_scatter(const int2* __restrict__ ind2v) {
    int p = blockIdx.x * blockDim.x + threadIdx.x;
    if (p < N_PAIRS) {
        int a = __ldg(&ind2v[p]).x;
        int pos = atomicAdd(&g_cursor[a], 1);
        if (pos < BCAP) g_bucket[a][pos] = p;
    }
}

// ---------------------------------------------------------------------------
// k_main: block = one atom, 128 threads = 4 warps (R11 shape).
// Packed-f32x2 math + packed smem metadata (int2 + float4) in the hot loop.
__global__ void __launch_bounds__(128, 8)
k_main(const int* __restrict__ ind2,
       const float* __restrict__ px,
       const float* __restrict__ i1,
       const float* __restrict__ diff,
       const float* __restrict__ wpp,
       float* __restrict__ out) {
    __shared__ int   s_pairs[BCAP];
    __shared__ __align__(8)  int2   s_pj[BCAP];   // (pair id, j)
    __shared__ __align__(16) float4 s_dv[BCAP];   // (d0, d1, d2, 0)
    __shared__ __align__(16) float s_part[4][3][NP];
    __shared__ __align__(16) float s_fin[3][NP];

    const int a = blockIdx.x;
    const int t = threadIdx.x;
    const int l = t & 31;
    const int y = t >> 5;
    const int q0 = 4 * l;

    // uniform broadcast read (all threads, same address -> one LDG)
    int c = g_cursor[a];
    const int cnt = c < BCAP ? c : BCAP;

    // stage pair list into smem (cnt <= 128, one per thread)
    if (t < cnt) s_pairs[t] = g_bucket[a][t];
    __syncthreads();

    // O(n^2) rank sort (deterministic order; pair ids distinct)
    int v = 0, r = 0;
    if (t < cnt) {
        v = s_pairs[t];
        for (int m = 0; m < cnt; m++) r += (s_pairs[m] < v);
    }
    __syncthreads();
    if (t < cnt) s_pairs[r] = v;
    __syncthreads();

    // prefetch j and diff, packed (parallel gathers, one per thread)
    if (t < cnt) {
        int pr = s_pairs[t];
        s_pj[t] = make_int2(pr, __ldg(&ind2[2 * pr + 1]));
        s_dv[t] = make_float4(__ldg(&diff[3 * pr + 0]),
                              __ldg(&diff[3 * pr + 1]),
                              __ldg(&diff[3 * pr + 2]), 0.f);
    }
    __syncthreads();

    float* out_ix = out + IX_OFF;

    U4 acc0, acc1, acc2;
    acc0.f = make_float4(0.f, 0.f, 0.f, 0.f);
    acc1.f = acc0.f; acc2.f = acc0.f;

    // main pair loop, 2x unrolled (8 loads in flight), packed math
    int k = y;
    for (; k + 4 < cnt; k += 8) {
        int2   pjA = s_pj[k];
        int2   pjB = s_pj[k + 4];
        float4 dA  = s_dv[k];
        float4 dB  = s_dv[k + 4];

        U4 sA, sB;
        sA.f = __ldcs((const float4*)(i1 + (size_t)pjA.x * NP + q0));
        sB.f = __ldcs((const float4*)(i1 + (size_t)pjB.x * NP + q0));
        const float* pjAp = px + (size_t)pjA.y * 3 * NP + q0;
        const float* pjBp = px + (size_t)pjB.y * 3 * NP + q0;
        float4 a0 = __ldg((const float4*)(pjAp));
        float4 a1 = __ldg((const float4*)(pjAp + NP));
        float4 a2v = __ldg((const float4*)(pjAp + 2 * NP));
        float4 b0 = __ldg((const float4*)(pjBp));
        float4 b1 = __ldg((const float4*)(pjBp + NP));
        float4 b2 = __ldg((const float4*)(pjBp + 2 * NP));

        U2 dA0, dA1, dA2, dB0, dB1, dB2;
        dA0.f = make_float2(dA.x, dA.x); dA1.f = make_float2(dA.y, dA.y);
        dA2.f = make_float2(dA.z, dA.z);
        dB0.f = make_float2(dB.x, dB.x); dB1.f = make_float2(dB.y, dB.y);
        dB2.f = make_float2(dB.z, dB.z);

        float4 vA0 = row_op(a0,  dA0.u, sA, acc0);
        float4 vA1 = row_op(a1,  dA1.u, sA, acc1);
        float4 vA2 = row_op(a2v, dA2.u, sA, acc2);
        float4 vB0 = row_op(b0,  dB0.u, sB, acc0);
        float4 vB1 = row_op(b1,  dB1.u, sB, acc1);
        float4 vB2 = row_op(b2,  dB2.u, sB, acc2);

        float* opA = out_ix + (size_t)pjA.x * 3 * NP + q0;
        float* opB = out_ix + (size_t)pjB.x * 3 * NP + q0;
        __stcs((float4*)(opA), vA0);
        __stcs((float4*)(opA + NP), vA1);
        __stcs((float4*)(opA + 2 * NP), vA2);
        __stcs((float4*)(opB), vB0);
        __stcs((float4*)(opB + NP), vB1);
        __stcs((float4*)(opB + 2 * NP), vB2);
    }
    for (; k < cnt; k += 4) {
        int2   pj = s_pj[k];
        float4 d  = s_dv[k];
        U4 s;
        s.f = __ldcs((const float4*)(i1 + (size_t)pj.x * NP + q0));
        const float* pjp = px + (size_t)pj.y * 3 * NP + q0;
        float4 p0 = __ldg((const float4*)(pjp));
        float4 p1 = __ldg((const float4*)(pjp + NP));
        float4 p2 = __ldg((const float4*)(pjp + 2 * NP));

        U2 d0, d1, d2;
        d0.f = make_float2(d.x, d.x);
        d1.f = make_float2(d.y, d.y);
        d2.f = make_float2(d.z, d.z);

        float4 v0 = row_op(p0, d0.u, s, acc0);
        float4 v1 = row_op(p1, d1.u, s, acc1);
        float4 v2 = row_op(p2, d2.u, s, acc2);

        float* op = out_ix + (size_t)pj.x * 3 * NP + q0;
        __stcs((float4*)(op), v0);
        __stcs((float4*)(op + NP), v1);
        __stcs((float4*)(op + 2 * NP), v2);
    }

    *(float4*)&s_part[y][0][q0] = acc0.f;
    *(float4*)&s_part[y][1][q0] = acc1.f;
    *(float4*)&s_part[y][2][q0] = acc2.f;
    __syncthreads();

    // reduce 4 partials -> s_fin (thread t owns channel t)
    {
        float f0 = s_part[0][0][t] + s_part[1][0][t] + s_part[2][0][t] + s_part[3][0][t];
        float f1 = s_part[0][1][t] + s_part[1][1][t] + s_part[2][1][t] + s_part[3][1][t];
        float f2 = s_part[0][2][t] + s_part[1][2][t] + s_part[2][2][t] + s_part[3][2][t];
        s_fin[0][t] = f0; s_fin[1][t] = f1; s_fin[2][t] = f2;
    }
    __syncthreads();

    // in-block GEMM (packed fma): warp y owns p-range [32y,32y+32)
    U4 o0, o1, o2;
    o0.f = make_float4(0.f, 0.f, 0.f, 0.f);
    o1.f = o0.f; o2.f = o0.f;
#pragma unroll 8
    for (int pp = 0; pp < 32; pp++) {
        int p = (y << 5) + pp;
        U4 w;
        w.f = *(const float4*)&wpp[(size_t)p * NO + q0];
        U2 a0p, a1p, a2p;
        float a0s = s_fin[0][p], a1s = s_fin[1][p], a2s = s_fin[2][p];
        a0p.f = make_float2(a0s, a0s);
        a1p.f = make_float2(a1s, a1s);
        a2p.f = make_float2(a2s, a2s);
        o0.u.x = fma2(a0p.u, w.u.x, o0.u.x); o0.u.y = fma2(a0p.u, w.u.y, o0.u.y);
        o1.u.x = fma2(a1p.u, w.u.x, o1.u.x); o1.u.y = fma2(a1p.u, w.u.y, o1.u.y);
        o2.u.x = fma2(a2p.u, w.u.x, o2.u.x); o2.u.y = fma2(a2p.u, w.u.y, o2.u.y);
    }
    __syncthreads();   // s_part reuse
    *(float4*)&s_part[y][0][q0] = o0.f;
    *(float4*)&s_part[y][1][q0] = o1.f;
    *(float4*)&s_part[y][2][q0] = o2.f;
    __syncthreads();

    // reduce GEMM partials over y, write px_new and dotted
    {
        float r0 = s_part[0][0][t] + s_part[1][0][t] + s_part[2][0][t] + s_part[3][0][t];
        float r1 = s_part[0][1][t] + s_part[1][1][t] + s_part[2][1][t] + s_part[3][1][t];
        float r2 = s_part[0][2][t] + s_part[1][2][t] + s_part[2][2][t] + s_part[3][2][t];
        float* opx = out + PXNEW_OFF + (size_t)a * 3 * NP + t;
        opx[0]      = r0;
        opx[NP]     = r1;
        opx[2 * NP] = r2;
        out[DOT_OFF + (size_t)a * NO + t] = r0 * r0 + r1 * r1 + r2 * r2;
    }

    // restore zero invariant for next graph replay (end of block, no sync)
    if (t == 0) g_cursor[a] = 0;
}

// ---------------------------------------------------------------------------
extern "C" void kernel_launch(void* const* d_in, const int* in_sizes, int n_in,
                              void* d_out, int out_size) {
    const int*   ind2 = (const int*)d_in[0];
    const float* px   = (const float*)d_in[1];
    const float* i1   = (const float*)d_in[2];
    const float* diff = (const float*)d_in[3];
    const float* wpp  = (const float*)d_in[4];
    float* out = (float*)d_out;

    k_scatter<<<(N_PAIRS + 255) / 256, 256>>>((const int2*)ind2);
    k_main<<<N_ATOMS, 128>>>(ind2, px, i1, diff, wpp, out);
}

// round 13
// speedup vs baseline: 1.0506x; 1.0506x over previous
#include <cuda_runtime.h>
#include <cstdint>
#include <cstddef>

#define N_ATOMS 10000
#define N_PAIRS 250000
#define NP 128
#define NO 128

#define PXNEW_OFF ((size_t)0)
#define IX_OFF    ((size_t)N_ATOMS * 3 * NP)
#define DOT_OFF   (IX_OFF + (size_t)N_PAIRS * 3 * NP)

#define BCAP 128   // per-atom bucket capacity; P(Poisson(25) >= 128) ~ 1e-45

// ---- device scratch (allocation-free; zero-initialized at load) ----
__device__ int    g_cursor[N_ATOMS];          // invariant: zero at entry (k_main end-resets)
__device__ int2   g_bpj[N_ATOMS][BCAP];       // (pair id, j)
__device__ float4 g_bd[N_ATOMS][BCAP];        // (d0, d1, d2, 0)

// ---------------------------------------------------------------------------
// packed f32x2 helpers (sm_103a; ptxas never emits these from C++)
typedef unsigned long long ull;
union U4 { float4 f; ulonglong2 u; };
union U2 { float2 f; ull u; };

__device__ __forceinline__ ull a2(ull a, ull b) {
    ull c; asm("add.rn.f32x2 %0,%1,%2;" : "=l"(c) : "l"(a), "l"(b)); return c;
}
__device__ __forceinline__ ull m2(ull a, ull b) {
    ull c; asm("mul.rn.f32x2 %0,%1,%2;" : "=l"(c) : "l"(a), "l"(b)); return c;
}
__device__ __forceinline__ ull fma2(ull a, ull b, ull c) {
    ull d; asm("fma.rn.f32x2 %0,%1,%2,%3;" : "=l"(d) : "l"(a), "l"(b), "l"(c)); return d;
}

// v = (p + dd) * s ; acc += v   (element-wise identical to scalar FADD/FMUL/FADD)
__device__ __forceinline__ float4 row_op(float4 p, ull dd, const U4& s, U4& acc) {
    U4 P, V;
    P.f = p;
    V.u.x = m2(a2(P.u.x, dd), s.u.x);
    V.u.y = m2(a2(P.u.y, dd), s.u.y);
    acc.u.x = a2(acc.u.x, V.u.x);
    acc.u.y = a2(acc.u.y, V.u.y);
    return V.f;
}

// ---------------------------------------------------------------------------
// scatter: bucket build + metadata gather in ONE pass (ind2/diff read coalesced
// here so k_main never does scattered 4B gathers).
__global__ void k_scatter(const int2* __restrict__ ind2v,
                          const float* __restrict__ diff) {
    int p = blockIdx.x * blockDim.x + threadIdx.x;
    if (p < N_PAIRS) {
        int2 v = __ldg(&ind2v[p]);            // v.x = a, v.y = j
        float d0 = __ldg(&diff[3 * p + 0]);
        float d1 = __ldg(&diff[3 * p + 1]);
        float d2 = __ldg(&diff[3 * p + 2]);
        int pos = atomicAdd(&g_cursor[v.x], 1);
        if (pos < BCAP) {
            g_bpj[v.x][pos] = make_int2(p, v.y);
            g_bd[v.x][pos]  = make_float4(d0, d1, d2, 0.f);
        }
    }
}

// ---------------------------------------------------------------------------
// k_main: block = one atom, 128 threads = 4 warps.
// Prologue: coalesced bucket loads (int2 + float4), rank sort carrying records.
// Pair loop: 2x unrolled (8 loads in flight), packed f32x2 math.
// Epilogue: partial reduce, in-block GEMM (w_pp L1-resident), px_new + dotted.
__global__ void __launch_bounds__(128, 8)
k_main(const float* __restrict__ px,
       const float* __restrict__ i1,
       const float* __restrict__ wpp,
       float* __restrict__ out) {
    __shared__ int   s_pairs[BCAP];
    __shared__ __align__(8)  int2   s_pj[BCAP];   // sorted (pair id, j)
    __shared__ __align__(16) float4 s_dv[BCAP];   // sorted (d0, d1, d2, 0)
    __shared__ __align__(16) float s_part[4][3][NP];
    __shared__ __align__(16) float s_fin[3][NP];

    const int a = blockIdx.x;
    const int t = threadIdx.x;
    const int l = t & 31;
    const int y = t >> 5;
    const int q0 = 4 * l;

    // uniform broadcast read (all threads, same address -> one LDG)
    int c = g_cursor[a];
    const int cnt = c < BCAP ? c : BCAP;

    // coalesced record loads (one per thread; cnt <= 128)
    int2 rec; float4 dv;
    if (t < cnt) {
        rec = __ldg(&g_bpj[a][t]);
        dv  = __ldg(&g_bd[a][t]);
        s_pairs[t] = rec.x;
    }
    __syncthreads();

    // O(n^2) rank sort by pair id (deterministic; ids distinct), carry records
    int r = 0;
    if (t < cnt) {
        int vv = rec.x;
        for (int m = 0; m < cnt; m++) r += (s_pairs[m] < vv);
        s_pj[r] = rec;
        s_dv[r] = dv;
    }
    __syncthreads();

    float* out_ix = out + IX_OFF;

    U4 acc0, acc1, acc2;
    acc0.f = make_float4(0.f, 0.f, 0.f, 0.f);
    acc1.f = acc0.f; acc2.f = acc0.f;

    // main pair loop, 2x unrolled (8 loads in flight), packed math
    int k = y;
    for (; k + 4 < cnt; k += 8) {
        int2   pjA = s_pj[k];
        int2   pjB = s_pj[k + 4];
        float4 dA  = s_dv[k];
        float4 dB  = s_dv[k + 4];

        U4 sA, sB;
        sA.f = __ldcs((const float4*)(i1 + (size_t)pjA.x * NP + q0));
        sB.f = __ldcs((const float4*)(i1 + (size_t)pjB.x * NP + q0));
        const float* pjAp = px + (size_t)pjA.y * 3 * NP + q0;
        const float* pjBp = px + (size_t)pjB.y * 3 * NP + q0;
        float4 a0 = __ldg((const float4*)(pjAp));
        float4 a1 = __ldg((const float4*)(pjAp + NP));
        float4 a2v = __ldg((const float4*)(pjAp + 2 * NP));
        float4 b0 = __ldg((const float4*)(pjBp));
        float4 b1 = __ldg((const float4*)(pjBp + NP));
        float4 b2 = __ldg((const float4*)(pjBp + 2 * NP));

        U2 dA0, dA1, dA2, dB0, dB1, dB2;
        dA0.f = make_float2(dA.x, dA.x); dA1.f = make_float2(dA.y, dA.y);
        dA2.f = make_float2(dA.z, dA.z);
        dB0.f = make_float2(dB.x, dB.x); dB1.f = make_float2(dB.y, dB.y);
        dB2.f = make_float2(dB.z, dB.z);

        float4 vA0 = row_op(a0,  dA0.u, sA, acc0);
        float4 vA1 = row_op(a1,  dA1.u, sA, acc1);
        float4 vA2 = row_op(a2v, dA2.u, sA, acc2);
        float4 vB0 = row_op(b0,  dB0.u, sB, acc0);
        float4 vB1 = row_op(b1,  dB1.u, sB, acc1);
        float4 vB2 = row_op(b2,  dB2.u, sB, acc2);

        float* opA = out_ix + (size_t)pjA.x * 3 * NP + q0;
        float* opB = out_ix + (size_t)pjB.x * 3 * NP + q0;
        __stcs((float4*)(opA), vA0);
        __stcs((float4*)(opA + NP), vA1);
        __stcs((float4*)(opA + 2 * NP), vA2);
        __stcs((float4*)(opB), vB0);
        __stcs((float4*)(opB + NP), vB1);
        __stcs((float4*)(opB + 2 * NP), vB2);
    }
    for (; k < cnt; k += 4) {
        int2   pj = s_pj[k];
        float4 d  = s_dv[k];
        U4 s;
        s.f = __ldcs((const float4*)(i1 + (size_t)pj.x * NP + q0));
        const float* pjp = px + (size_t)pj.y * 3 * NP + q0;
        float4 p0 = __ldg((const float4*)(pjp));
        float4 p1 = __ldg((const float4*)(pjp + NP));
        float4 p2 = __ldg((const float4*)(pjp + 2 * NP));

        U2 d0, d1, d2;
        d0.f = make_float2(d.x, d.x);
        d1.f = make_float2(d.y, d.y);
        d2.f = make_float2(d.z, d.z);

        float4 v0 = row_op(p0, d0.u, s, acc0);
        float4 v1 = row_op(p1, d1.u, s, acc1);
        float4 v2 = row_op(p2, d2.u, s, acc2);

        float* op = out_ix + (size_t)pj.x * 3 * NP + q0;
        __stcs((float4*)(op), v0);
        __stcs((float4*)(op + NP), v1);
        __stcs((float4*)(op + 2 * NP), v2);
    }

    *(float4*)&s_part[y][0][q0] = acc0.f;
    *(float4*)&s_part[y][1][q0] = acc1.f;
    *(float4*)&s_part[y][2][q0] = acc2.f;
    __syncthreads();

    // reduce 4 partials -> s_fin (thread t owns channel t)
    {
        float f0 = s_part[0][0][t] + s_part[1][0][t] + s_part[2][0][t] + s_part[3][0][t];
        float f1 = s_part[0][1][t] + s_part[1][1][t] + s_part[2][1][t] + s_part[3][1][t];
        float f2 = s_part[0][2][t] + s_part[1][2][t] + s_part[2][2][t] + s_part[3][2][t];
        s_fin[0][t] = f0; s_fin[1][t] = f1; s_fin[2][t] = f2;
    }
    __syncthreads();

    // in-block GEMM (packed fma): warp y owns p-range [32y,32y+32)
    U4 o0, o1, o2;
    o0.f = make_float4(0.f, 0.f, 0.f, 0.f);
    o1.f = o0.f; o2.f = o0.f;
#pragma unroll 8
    for (int pp = 0; pp < 32; pp++) {
        int p = (y << 5) + pp;
        U4 w;
        w.f = *(const float4*)&wpp[(size_t)p * NO + q0];
        U2 a0p, a1p, a2p;
        float a0s = s_fin[0][p], a1s = s_fin[1][p], a2s = s_fin[2][p];
        a0p.f = make_float2(a0s, a0s);
        a1p.f = make_float2(a1s, a1s);
        a2p.f = make_float2(a2s, a2s);
        o0.u.x = fma2(a0p.u, w.u.x, o0.u.x); o0.u.y = fma2(a0p.u, w.u.y, o0.u.y);
        o1.u.x = fma2(a1p.u, w.u.x, o1.u.x); o1.u.y = fma2(a1p.u, w.u.y, o1.u.y);
        o2.u.x = fma2(a2p.u, w.u.x, o2.u.x); o2.u.y = fma2(a2p.u, w.u.y, o2.u.y);
    }
    __syncthreads();   // s_part reuse
    *(float4*)&s_part[y][0][q0] = o0.f;
    *(float4*)&s_part[y][1][q0] = o1.f;
    *(float4*)&s_part[y][2][q0] = o2.f;
    __syncthreads();

    // reduce GEMM partials over y, write px_new and dotted
    {
        float r0 = s_part[0][0][t] + s_part[1][0][t] + s_part[2][0][t] + s_part[3][0][t];
        float r1 = s_part[0][1][t] + s_part[1][1][t] + s_part[2][1][t] + s_part[3][1][t];
        float r2 = s_part[0][2][t] + s_part[1][2][t] + s_part[2][2][t] + s_part[3][2][t];
        float* opx = out + PXNEW_OFF + (size_t)a * 3 * NP + t;
        opx[0]      = r0;
        opx[NP]     = r1;
        opx[2 * NP] = r2;
        out[DOT_OFF + (size_t)a * NO + t] = r0 * r0 + r1 * r1 + r2 * r2;
    }

    // restore zero invariant for next graph replay (end of block, no sync)
    if (t == 0) g_cursor[a] = 0;
}

// ---------------------------------------------------------------------------
extern "C" void kernel_launch(void* const* d_in, const int* in_sizes, int n_in,
                              void* d_out, int out_size) {
    const int*   ind2 = (const int*)d_in[0];
    const float* px   = (const float*)d_in[1];
    const float* i1   = (const float*)d_in[2];
    const float* diff = (const float*)d_in[3];
    const float* wpp  = (const float*)d_in[4];
    float* out = (float*)d_out;

    k_scatter<<<(N_PAIRS + 255) / 256, 256>>>((const int2*)ind2, diff);
    k_main<<<N_ATOMS, 128>>>(px, i1, wpp, out);
}

// round 14
// speedup vs baseline: 1.0530x; 1.0023x over previous
#include <cuda_runtime.h>
#include <cstdint>
#include <cstddef>

#define N_ATOMS 10000
#define N_PAIRS 250000
#define NP 128
#define NO 128

#define PXNEW_OFF ((size_t)0)
#define IX_OFF    ((size_t)N_ATOMS * 3 * NP)
#define DOT_OFF   (IX_OFF + (size_t)N_PAIRS * 3 * NP)

#define BCAP 128   // per-atom bucket capacity; P(Poisson(25) >= 128) ~ 1e-45

// ---- device scratch (allocation-free; zero-initialized at load) ----
__device__ int    g_cursor[N_ATOMS];          // invariant: zero at entry (k_main end-resets)
__device__ int2   g_bpj[N_ATOMS][BCAP];       // (pair id, j)
__device__ float4 g_bd[N_ATOMS][BCAP];        // (d0, d1, d2, 0)

// ---------------------------------------------------------------------------
// packed f32x2 helpers (sm_103a; ptxas never emits these from C++)
typedef unsigned long long ull;
union U4 { float4 f; ulonglong2 u; };
union U2 { float2 f; ull u; };

__device__ __forceinline__ ull a2(ull a, ull b) {
    ull c; asm("add.rn.f32x2 %0,%1,%2;" : "=l"(c) : "l"(a), "l"(b)); return c;
}
__device__ __forceinline__ ull m2(ull a, ull b) {
    ull c; asm("mul.rn.f32x2 %0,%1,%2;" : "=l"(c) : "l"(a), "l"(b)); return c;
}
__device__ __forceinline__ ull fma2(ull a, ull b, ull c) {
    ull d; asm("fma.rn.f32x2 %0,%1,%2,%3;" : "=l"(d) : "l"(a), "l"(b), "l"(c)); return d;
}

// v = (p + dd) * s ; acc += v   (element-wise identical to scalar FADD/FMUL/FADD)
__device__ __forceinline__ float4 row_op(float4 p, ull dd, const U4& s, U4& acc) {
    U4 P, V;
    P.f = p;
    V.u.x = m2(a2(P.u.x, dd), s.u.x);
    V.u.y = m2(a2(P.u.y, dd), s.u.y);
    acc.u.x = a2(acc.u.x, V.u.x);
    acc.u.y = a2(acc.u.y, V.u.y);
    return V.f;
}

// ---------------------------------------------------------------------------
// scatter: bucket build + metadata gather in ONE pass, 2 pairs per thread.
// ind2 read as int4 (pairs 2i, 2i+1); diff rows read as 3x float2 (aligned).
__global__ void k_scatter(const int4* __restrict__ ind2v4,
                          const float2* __restrict__ diffv2) {
    int i = blockIdx.x * blockDim.x + threadIdx.x;
    if (i < N_PAIRS / 2) {
        int4 v = __ldg(&ind2v4[i]);          // pair 2i: (a=v.x, j=v.y); 2i+1: (a=v.z, j=v.w)
        float2 da = __ldg(&diffv2[3 * i + 0]);   // d[2i].x,   d[2i].y
        float2 db = __ldg(&diffv2[3 * i + 1]);   // d[2i].z,   d[2i+1].x
        float2 dc = __ldg(&diffv2[3 * i + 2]);   // d[2i+1].y, d[2i+1].z

        int p0 = 2 * i, p1 = 2 * i + 1;
        int pos0 = atomicAdd(&g_cursor[v.x], 1);
        if (pos0 < BCAP) {
            g_bpj[v.x][pos0] = make_int2(p0, v.y);
            g_bd[v.x][pos0]  = make_float4(da.x, da.y, db.x, 0.f);
        }
        int pos1 = atomicAdd(&g_cursor[v.z], 1);
        if (pos1 < BCAP) {
            g_bpj[v.z][pos1] = make_int2(p1, v.w);
            g_bd[v.z][pos1]  = make_float4(db.y, dc.x, dc.y, 0.f);
        }
    }
}

// ---------------------------------------------------------------------------
// k_main: block = one atom, 128 threads = 4 warps.
// Prologue: coalesced bucket loads, rank sort carrying records.
// Pair loop: 2x unrolled (8 loads in flight), packed f32x2 math.
// GEMM: warp y owns p-range [32y,32y+32); s_fin read via LDS.128 (4 p / load).
__global__ void __launch_bounds__(128, 8)
k_main(const float* __restrict__ px,
       const float* __restrict__ i1,
       const float* __restrict__ wpp,
       float* __restrict__ out) {
    __shared__ int   s_pairs[BCAP];
    __shared__ __align__(8)  int2   s_pj[BCAP];   // sorted (pair id, j)
    __shared__ __align__(16) float4 s_dv[BCAP];   // sorted (d0, d1, d2, 0)
    __shared__ __align__(16) float s_part[4][3][NP];
    __shared__ __align__(16) float s_fin[3][NP];

    const int a = blockIdx.x;
    const int t = threadIdx.x;
    const int l = t & 31;
    const int y = t >> 5;
    const int q0 = 4 * l;

    // uniform broadcast read (all threads, same address -> one LDG)
    int c = g_cursor[a];
    const int cnt = c < BCAP ? c : BCAP;

    // coalesced record loads (one per thread; cnt <= 128)
    int2 rec; float4 dv;
    if (t < cnt) {
        rec = __ldg(&g_bpj[a][t]);
        dv  = __ldg(&g_bd[a][t]);
        s_pairs[t] = rec.x;
    }
    __syncthreads();

    // O(n^2) rank sort by pair id (deterministic; ids distinct), carry records
    int r = 0;
    if (t < cnt) {
        int vv = rec.x;
        for (int m = 0; m < cnt; m++) r += (s_pairs[m] < vv);
        s_pj[r] = rec;
        s_dv[r] = dv;
    }
    __syncthreads();

    float* out_ix = out + IX_OFF;

    U4 acc0, acc1, acc2;
    acc0.f = make_float4(0.f, 0.f, 0.f, 0.f);
    acc1.f = acc0.f; acc2.f = acc0.f;

    // main pair loop, 2x unrolled (8 loads in flight), packed math
    int k = y;
    for (; k + 4 < cnt; k += 8) {
        int2   pjA = s_pj[k];
        int2   pjB = s_pj[k + 4];
        float4 dA  = s_dv[k];
        float4 dB  = s_dv[k + 4];

        U4 sA, sB;
        sA.f = __ldcs((const float4*)(i1 + (size_t)pjA.x * NP + q0));
        sB.f = __ldcs((const float4*)(i1 + (size_t)pjB.x * NP + q0));
        const float* pjAp = px + (size_t)pjA.y * 3 * NP + q0;
        const float* pjBp = px + (size_t)pjB.y * 3 * NP + q0;
        float4 a0 = __ldg((const float4*)(pjAp));
        float4 a1 = __ldg((const float4*)(pjAp + NP));
        float4 a2v = __ldg((const float4*)(pjAp + 2 * NP));
        float4 b0 = __ldg((const float4*)(pjBp));
        float4 b1 = __ldg((const float4*)(pjBp + NP));
        float4 b2 = __ldg((const float4*)(pjBp + 2 * NP));

        U2 dA0, dA1, dA2, dB0, dB1, dB2;
        dA0.f = make_float2(dA.x, dA.x); dA1.f = make_float2(dA.y, dA.y);
        dA2.f = make_float2(dA.z, dA.z);
        dB0.f = make_float2(dB.x, dB.x); dB1.f = make_float2(dB.y, dB.y);
        dB2.f = make_float2(dB.z, dB.z);

        float4 vA0 = row_op(a0,  dA0.u, sA, acc0);
        float4 vA1 = row_op(a1,  dA1.u, sA, acc1);
        float4 vA2 = row_op(a2v, dA2.u, sA, acc2);
        float4 vB0 = row_op(b0,  dB0.u, sB, acc0);
        float4 vB1 = row_op(b1,  dB1.u, sB, acc1);
        float4 vB2 = row_op(b2,  dB2.u, sB, acc2);

        float* opA = out_ix + (size_t)pjA.x * 3 * NP + q0;
        float* opB = out_ix + (size_t)pjB.x * 3 * NP + q0;
        __stcs((float4*)(opA), vA0);
        __stcs((float4*)(opA + NP), vA1);
        __stcs((float4*)(opA + 2 * NP), vA2);
        __stcs((float4*)(opB), vB0);
        __stcs((float4*)(opB + NP), vB1);
        __stcs((float4*)(opB + 2 * NP), vB2);
    }
    for (; k < cnt; k += 4) {
        int2   pj = s_pj[k];
        float4 d  = s_dv[k];
        U4 s;
        s.f = __ldcs((const float4*)(i1 + (size_t)pj.x * NP + q0));
        const float* pjp = px + (size_t)pj.y * 3 * NP + q0;
        float4 p0 = __ldg((const float4*)(pjp));
        float4 p1 = __ldg((const float4*)(pjp + NP));
        float4 p2 = __ldg((const float4*)(pjp + 2 * NP));

        U2 d0, d1, d2;
        d0.f = make_float2(d.x, d.x);
        d1.f = make_float2(d.y, d.y);
        d2.f = make_float2(d.z, d.z);

        float4 v0 = row_op(p0, d0.u, s, acc0);
        float4 v1 = row_op(p1, d1.u, s, acc1);
        float4 v2 = row_op(p2, d2.u, s, acc2);

        float* op = out_ix + (size_t)pj.x * 3 * NP + q0;
        __stcs((float4*)(op), v0);
        __stcs((float4*)(op + NP), v1);
        __stcs((float4*)(op + 2 * NP), v2);
    }

    *(float4*)&s_part[y][0][q0] = acc0.f;
    *(float4*)&s_part[y][1][q0] = acc1.f;
    *(float4*)&s_part[y][2][q0] = acc2.f;
    __syncthreads();

    // reduce 4 partials -> s_fin (thread t owns channel t)
    {
        float f0 = s_part[0][0][t] + s_part[1][0][t] + s_part[2][0][t] + s_part[3][0][t];
        float f1 = s_part[0][1][t] + s_part[1][1][t] + s_part[2][1][t] + s_part[3][1][t];
        float f2 = s_part[0][2][t] + s_part[1][2][t] + s_part[2][2][t] + s_part[3][2][t];
        s_fin[0][t] = f0; s_fin[1][t] = f1; s_fin[2][t] = f2;
    }
    __syncthreads();

    // in-block GEMM (packed fma): warp y owns p-range [32y,32y+32).
    // s_fin read as float4 (4 p-steps per LDS.128); p order unchanged.
    U4 o0, o1, o2;
    o0.f = make_float4(0.f, 0.f, 0.f, 0.f);
    o1.f = o0.f; o2.f = o0.f;
#pragma unroll
    for (int pp = 0; pp < 32; pp += 4) {
        int p = (y << 5) + pp;
        float4 f0v = *(const float4*)&s_fin[0][p];
        float4 f1v = *(const float4*)&s_fin[1][p];
        float4 f2v = *(const float4*)&s_fin[2][p];
        const float f0a[4] = { f0v.x, f0v.y, f0v.z, f0v.w };
        const float f1a[4] = { f1v.x, f1v.y, f1v.z, f1v.w };
        const float f2a[4] = { f2v.x, f2v.y, f2v.z, f2v.w };
#pragma unroll
        for (int i = 0; i < 4; i++) {
            U4 w;
            w.f = *(const float4*)&wpp[(size_t)(p + i) * NO + q0];
            U2 a0p, a1p, a2p;
            a0p.f = make_float2(f0a[i], f0a[i]);
            a1p.f = make_float2(f1a[i], f1a[i]);
            a2p.f = make_float2(f2a[i], f2a[i]);
            o0.u.x = fma2(a0p.u, w.u.x, o0.u.x); o0.u.y = fma2(a0p.u, w.u.y, o0.u.y);
            o1.u.x = fma2(a1p.u, w.u.x, o1.u.x); o1.u.y = fma2(a1p.u, w.u.y, o1.u.y);
            o2.u.x = fma2(a2p.u, w.u.x, o2.u.x); o2.u.y = fma2(a2p.u, w.u.y, o2.u.y);
        }
    }
    __syncthreads();   // s_part reuse
    *(float4*)&s_part[y][0][q0] = o0.f;
    *(float4*)&s_part[y][1][q0] = o1.f;
    *(float4*)&s_part[y][2][q0] = o2.f;
    __syncthreads();

    // reduce GEMM partials over y, write px_new and dotted
    {
        float r0 = s_part[0][0][t] + s_part[1][0][t] + s_part[2][0][t] + s_part[3][0][t];
        float r1 = s_part[0][1][t] + s_part[1][1][t] + s_part[2][1][t] + s_part[3][1][t];
        float r2 = s_part[0][2][t] + s_part[1][2][t] + s_part[2][2][t] + s_part[3][2][t];
        float* opx = out + PXNEW_OFF + (size_t)a * 3 * NP + t;
        opx[0]      = r0;
        opx[NP]     = r1;
        opx[2 * NP] = r2;
        out[DOT_OFF + (size_t)a * NO + t] = r0 * r0 + r1 * r1 + r2 * r2;
    }

    // restore zero invariant for next graph replay (end of block, no sync)
    if (t == 0) g_cursor[a] = 0;
}

// ---------------------------------------------------------------------------
extern "C" void kernel_launch(void* const* d_in, const int* in_sizes, int n_in,
                              void* d_out, int out_size) {
    const int*   ind2 = (const int*)d_in[0];
    const float* px   = (const float*)d_in[1];
    const float* i1   = (const float*)d_in[2];
    const float* diff = (const float*)d_in[3];
    const float* wpp  = (const float*)d_in[4];
    float* out = (float*)d_out;

    k_scatter<<<(N_PAIRS / 2 + 255) / 256, 256>>>((const int4*)ind2,
                                                  (const float2*)diff);
    k_main<<<N_ATOMS, 128>>>(px, i1, wpp, out);
}